// round 15
// baseline (speedup 1.0000x reference)
#include <cuda_runtime.h>
#include <cuda_fp16.h>
#include <math.h>
#include <stdint.h>

// ---------------------------------------------------------------------------
// FormationOptimizer: fully-connected GNN, N=512, 3 message-passing rounds.
// Edge layer0 factorized: A[i] + B[j] + dist*wd (fp32). Edge MLP GEMMs on
// tensor cores via mma.sync.m16n8k16 fp16 with ldmatrix fragment loads.
// 1 CTA/SM, 320 threads = 5 independent 2-warp pipelines (named barriers);
// full W1+W2 fragment sets in registers (204-reg budget at 320 thr).
// ---------------------------------------------------------------------------

#define NN 512
#define FD 64
#define H0D 128

__device__ float g_NF[NN * FD];
__device__ float g_DIST[NN * NN];
__device__ float g_A[NN * H0D];      // nf @ ew0[0:64]        [node][k]
__device__ float g_B[NN * H0D];      // nf @ ew0[64:128]+eb0  [node][k]
__device__ float g_AGG[NN * 32];

__device__ __forceinline__ uint32_t pack_h2(float lo, float hi) {
    __half2 h = __floats2half2_rn(lo, hi);
    return *(uint32_t*)&h;
}
__device__ __forceinline__ void mma16(float* c, const uint32_t* a, const uint32_t* b) {
    asm volatile(
        "mma.sync.aligned.m16n8k16.row.col.f32.f16.f16.f32 "
        "{%0,%1,%2,%3}, {%4,%5,%6,%7}, {%8,%9}, {%0,%1,%2,%3};"
        : "+f"(c[0]), "+f"(c[1]), "+f"(c[2]), "+f"(c[3])
        : "r"(a[0]), "r"(a[1]), "r"(a[2]), "r"(a[3]), "r"(b[0]), "r"(b[1]));
}
__device__ __forceinline__ void ldsm4(uint32_t* r, uint32_t saddr) {
    asm volatile(
        "ldmatrix.sync.aligned.m8n8.x4.shared.b16 {%0,%1,%2,%3}, [%4];"
        : "=r"(r[0]), "=r"(r[1]), "=r"(r[2]), "=r"(r[3]) : "r"(saddr));
}
__device__ __forceinline__ void pair_bar(int id) {
    asm volatile("bar.sync %0, 64;" :: "r"(id) : "memory");
}

// ---------------------------------------------------------------------------
__global__ void k_init_nf(const float* __restrict__ states,
                          const float* __restrict__ obj) {
    int idx = blockIdx.x * 256 + threadIdx.x;
    int i = idx >> 6, c = idx & 63;
    g_NF[idx] = (c < 6) ? states[i * 6 + c] : obj[c - 6];
}

__global__ void k_init_dist(const float* __restrict__ states) {
    int i = blockIdx.x, t = threadIdx.x;
    float px = states[i * 6 + 0], py = states[i * 6 + 1], pz = states[i * 6 + 2];
    for (int j = t; j < NN; j += blockDim.x) {
        float dx = states[j * 6 + 0] - px;
        float dy = states[j * 6 + 1] - py;
        float dz = states[j * 6 + 2] - pz;
        g_DIST[i * NN + j] = sqrtf(dx * dx + dy * dy + dz * dz);
    }
}

// ---------------------------------------------------------------------------
// k_proj: A/B for iteration 0, zero g_AGG.
// ---------------------------------------------------------------------------
#define PROJ_SMEM (16384 + 512)
__global__ void __launch_bounds__(256) k_proj(const float* __restrict__ ew0,
                                              const float* __restrict__ eb0) {
    extern __shared__ float sm[];
    float* sE = sm;
    float* snf = sm + 16384;
    const int t = threadIdx.x;
    const int nb8 = blockIdx.x * 8;

    for (int q = 0; q < 16; q++)
        *(float4*)(sE + q * 1024 + t * 4) = *(const float4*)(ew0 + q * 1024 + t * 4);
    for (int q = 0; q < 2; q++)
        snf[q * 256 + t] = g_NF[nb8 * 64 + q * 256 + t];
    g_AGG[blockIdx.x * 256 + t] = 0.f;
    __syncthreads();

    const int nd = t >> 5;
    const int k4 = (t & 31) * 4;
    float4 a = make_float4(0.f, 0.f, 0.f, 0.f);
    float4 b = make_float4(0.f, 0.f, 0.f, 0.f);
#pragma unroll 4
    for (int c = 0; c < 64; c++) {
        float v = snf[nd * 64 + c];
        float4 wa = *(const float4*)(sE + c * 128 + k4);
        float4 wb = *(const float4*)(sE + (64 + c) * 128 + k4);
        a.x = fmaf(v, wa.x, a.x); a.y = fmaf(v, wa.y, a.y);
        a.z = fmaf(v, wa.z, a.z); a.w = fmaf(v, wa.w, a.w);
        b.x = fmaf(v, wb.x, b.x); b.y = fmaf(v, wb.y, b.y);
        b.z = fmaf(v, wb.z, b.z); b.w = fmaf(v, wb.w, b.w);
    }
    float4 e = *(const float4*)(eb0 + k4);
    b.x += e.x; b.y += e.y; b.z += e.z; b.w += e.w;
    *(float4*)(g_A + (nb8 + nd) * 128 + k4) = a;
    *(float4*)(g_B + (nb8 + nd) * 128 + k4) = b;
}

// ---------------------------------------------------------------------------
// k_edge: persistent fp16 mma, grid=148 (1 CTA/SM), 320 threads.
// 5 independent warp-pairs per CTA; sub-item = (j, 32-sender tile).
// NITEM_S = 8192 sub-items over 740 pair-pipelines.
// smem words: W1t[64][68] | W2t[32][36] | 5x H0p[32][68] | 5x H1p[32][36]
// ---------------------------------------------------------------------------
#define S_W1T 0
#define S_W2T 4352
#define S_H0  5504
#define S_H1  16384
#define E_SMEMW 22144    // words -> 88576 bytes

#define NITEM_S 8192
#define EGRID 148
#define NPAIR 5
#define NPIPE (EGRID * NPAIR)
#define ETHREADS (NPAIR * 64)

// H0p[e][k] = relu(A[i][k] + B[j][k] + d*wd[k]); warp wp builds rows
// [16*wp, 16*wp+16) of its pair's 32-edge tile.
__device__ __forceinline__ void compute_H0(uint32_t* __restrict__ sH0p,
                                           int s, int wp, int lane,
                                           const float* __restrict__ ew0)
{
    const int j = s >> 4;
    const int eb = (s & 15) * 32 + 16 * wp;
    const float4 wv = __ldg((const float4*)(ew0 + 128 * H0D) + lane);
    float dl = 0.f;
    if (lane < 16) dl = __ldg(g_DIST + j * NN + eb + lane);
    const float4 bv = __ldg((const float4*)(g_B + j * H0D) + lane);
    uint32_t* dst = sH0p + (16 * wp) * 68 + 2 * lane;
#pragma unroll
    for (int e = 0; e < 16; e++) {
        float d = __shfl_sync(0xffffffffu, dl, e);
        float4 av = __ldg((const float4*)(g_A + (eb + e) * H0D) + lane);
        float h0 = fmaxf(fmaf(d, wv.x, av.x + bv.x), 0.f);
        float h1 = fmaxf(fmaf(d, wv.y, av.y + bv.y), 0.f);
        float h2 = fmaxf(fmaf(d, wv.z, av.z + bv.z), 0.f);
        float h3 = fmaxf(fmaf(d, wv.w, av.w + bv.w), 0.f);
        uint2 u;
        u.x = pack_h2(h0, h1);
        u.y = pack_h2(h2, h3);
        *(uint2*)(dst + e * 68) = u;
    }
}

__global__ void __launch_bounds__(ETHREADS, 1) k_edge(
    const float* __restrict__ ew0, const float* __restrict__ ew1,
    const float* __restrict__ eb1, const float* __restrict__ ew2,
    const float* __restrict__ eb2)
{
    extern __shared__ uint32_t smw[];
    uint32_t* sW1tw = smw + S_W1T;
    uint32_t* sW2tw = smw + S_W2T;
    const uint32_t sb = (uint32_t)__cvta_generic_to_shared(smw);

    const int t = threadIdx.x;
    const int lane = t & 31;
    const int w = t >> 5;
    const int p  = w >> 1;     // pair 0..4
    const int wp = w & 1;      // warp-in-pair
    const int ar = lane >> 2;
    const int ac = lane & 3;

    uint32_t* sH0p = smw + S_H0 + p * (32 * 68);

    // ---- stage weights (transposed, fp16 pairs) once per CTA ----
    for (int idx = t; idx < 4096; idx += ETHREADS) {
        int n = idx >> 6, wk = idx & 63;
        sW1tw[n * 68 + wk] = pack_h2(__ldg(ew1 + (2 * wk) * 64 + n),
                                     __ldg(ew1 + (2 * wk + 1) * 64 + n));
    }
    for (int idx = t; idx < 1024; idx += ETHREADS) {
        int m = idx >> 5, wk = idx & 31;
        sW2tw[m * 36 + wk] = pack_h2(__ldg(ew2 + (2 * wk) * 32 + m),
                                     __ldg(ew2 + (2 * wk + 1) * 32 + m));
    }

    // ldmatrix per-lane offsets (word units)
    const int lrowA = ((lane >> 3) & 1) * 8 + (lane & 7);
    const int lcolA = (lane >> 4) * 4;
    const int lrowB = ((lane >> 4) & 1) * 8 + (lane & 7);
    const int lcolB = ((lane >> 3) & 1) * 4;

    // GEMM1: pair tile 32e x 64n; this warp covers n [nw, nw+32)
    const int nw = wp * 32;
    float e1b[4][2];
#pragma unroll
    for (int ni = 0; ni < 4; ni++) {
        e1b[ni][0] = __ldg(eb1 + nw + ni * 8 + 2 * ac);
        e1b[ni][1] = __ldg(eb1 + nw + ni * 8 + 2 * ac + 1);
    }
    // GEMM2: pair tile 32e x 32m; this warp covers m [mb2, mb2+16)
    const int mb2 = wp * 16;
    float e2b[2][2];
#pragma unroll
    for (int ni = 0; ni < 2; ni++) {
        e2b[ni][0] = __ldg(eb2 + mb2 + ni * 8 + 2 * ac);
        e2b[ni][1] = __ldg(eb2 + mb2 + ni * 8 + 2 * ac + 1);
    }

    // ldmatrix base addresses (bytes)
    const uint32_t h0base = sb + (S_H0 + p * (32 * 68)) * 4;
    const uint32_t aH0_0 = h0base + (lrowA * 68 + lcolA) * 4;
    const uint32_t aH0_1 = aH0_0 + 16 * 68 * 4;
    const uint32_t aW1_0 = sb + (S_W1T + (nw + lrowB) * 68 + lcolB) * 4;
    const uint32_t aW1_1 = aW1_0 + 16 * 68 * 4;
    const uint32_t h1base = sb + (S_H1 + p * (32 * 36)) * 4;
    const uint32_t aH1_0 = h1base + (lrowA * 36 + lcolA) * 4;
    const uint32_t aH1_1 = aH1_0 + 16 * 36 * 4;
    const uint32_t aW2   = sb + (S_W2T + (mb2 + lrowB) * 36 + lcolB) * 4;

    __syncthreads();   // weights staged (only CTA-wide sync)

    // ---- register-resident fragments: ALL of W1 (64 regs) + W2 (16 regs) ----
    uint32_t w1f[8][8];
#pragma unroll
    for (int ks = 0; ks < 8; ks++) {
        ldsm4(&w1f[ks][0], aW1_0 + ks * 32);
        ldsm4(&w1f[ks][4], aW1_1 + ks * 32);
    }
    uint32_t w2f[4][4];
#pragma unroll
    for (int ks = 0; ks < 4; ks++)
        ldsm4(w2f[ks], aW2 + ks * 32);

    const int bid = p + 1;                    // named barrier id for this pair
    int s = blockIdx.x * NPAIR + p;           // sub-item index for this pipeline
    if (s < NITEM_S)
        compute_H0(sH0p, s, wp, lane, ew0);
    pair_bar(bid);

    while (s < NITEM_S) {
        const int j = s >> 4;
        const int ibase = (s & 15) * 32;

        // ================ GEMM1: H1p = relu(H0p @ W1 + b1) ================
        {
            float acc[2][4][4];
#pragma unroll
            for (int mi = 0; mi < 2; mi++)
#pragma unroll
                for (int ni = 0; ni < 4; ni++) {
                    acc[mi][ni][0] = e1b[ni][0];
                    acc[mi][ni][1] = e1b[ni][1];
                    acc[mi][ni][2] = e1b[ni][0];
                    acc[mi][ni][3] = e1b[ni][1];
                }
#pragma unroll
            for (int ks = 0; ks < 8; ks++) {
                const uint32_t koff = ks * 8 * 4;
                uint32_t a[2][4];
                ldsm4(a[0], aH0_0 + koff);
                ldsm4(a[1], aH0_1 + koff);
#pragma unroll
                for (int mi = 0; mi < 2; mi++)
#pragma unroll
                    for (int ni = 0; ni < 4; ni++)
                        mma16(acc[mi][ni], a[mi],
                              &w1f[ks][(ni >> 1) * 4 + (ni & 1) * 2]);
            }
            // epilogue: relu -> fp16 pairs into H1p
            uint32_t* h1w = smw + S_H1 + p * (32 * 36);
#pragma unroll
            for (int mi = 0; mi < 2; mi++) {
                const int r0 = mi * 16 + ar;
#pragma unroll
                for (int ni = 0; ni < 4; ni++) {
                    const int wc = (nw >> 1) + ni * 4 + ac;
                    h1w[r0 * 36 + wc] =
                        pack_h2(fmaxf(acc[mi][ni][0], 0.f), fmaxf(acc[mi][ni][1], 0.f));
                    h1w[(r0 + 8) * 36 + wc] =
                        pack_h2(fmaxf(acc[mi][ni][2], 0.f), fmaxf(acc[mi][ni][3], 0.f));
                }
            }
        }
        pair_bar(bid);   // H1p ready; H0p free

        // ================ GEMM2 + masked reduction ================
        {
            float acc[2][2][4];
#pragma unroll
            for (int mi = 0; mi < 2; mi++)
#pragma unroll
                for (int ni = 0; ni < 2; ni++) {
                    acc[mi][ni][0] = e2b[ni][0];
                    acc[mi][ni][1] = e2b[ni][1];
                    acc[mi][ni][2] = e2b[ni][0];
                    acc[mi][ni][3] = e2b[ni][1];
                }
#pragma unroll
            for (int ks = 0; ks < 4; ks++) {
                const uint32_t koff = ks * 8 * 4;
                uint32_t a[2][4];
                ldsm4(a[0], aH1_0 + koff);
                ldsm4(a[1], aH1_1 + koff);
#pragma unroll
                for (int mi = 0; mi < 2; mi++) {
                    mma16(acc[mi][0], a[mi], &w2f[ks][0]);
                    mma16(acc[mi][1], a[mi], &w2f[ks][2]);
                }
            }
            float sacc[2][2] = {{0.f, 0.f}, {0.f, 0.f}};
#pragma unroll
            for (int mi = 0; mi < 2; mi++) {
                const int i0 = ibase + mi * 16 + ar;
                const bool k0 = (i0 != j);
                const bool k1 = (i0 + 8 != j);
#pragma unroll
                for (int ni = 0; ni < 2; ni++) {
                    if (k0) {
                        sacc[ni][0] += fmaxf(acc[mi][ni][0], 0.f);
                        sacc[ni][1] += fmaxf(acc[mi][ni][1], 0.f);
                    }
                    if (k1) {
                        sacc[ni][0] += fmaxf(acc[mi][ni][2], 0.f);
                        sacc[ni][1] += fmaxf(acc[mi][ni][3], 0.f);
                    }
                }
            }
#pragma unroll
            for (int off = 4; off <= 16; off <<= 1) {
#pragma unroll
                for (int ni = 0; ni < 2; ni++) {
                    sacc[ni][0] += __shfl_xor_sync(0xffffffffu, sacc[ni][0], off);
                    sacc[ni][1] += __shfl_xor_sync(0xffffffffu, sacc[ni][1], off);
                }
            }
            if (lane < 4) {
                float* dst = g_AGG + j * 32 + mb2 + 2 * ac;
                atomicAdd(dst + 0, sacc[0][0]);
                atomicAdd(dst + 1, sacc[0][1]);
                atomicAdd(dst + 8, sacc[1][0]);
                atomicAdd(dst + 9, sacc[1][1]);
            }
        }

        // H0p for next sub-item (H0p free since previous pair_bar)
        const int nxt = s + NPIPE;
        if (nxt < NITEM_S)
            compute_H0(sH0p, nxt, wp, lane, ew0);
        pair_bar(bid);   // H0p ready; H1p free
        s = nxt;
    }
}

// ---------------------------------------------------------------------------
// k_node: 256 CTAs x 2 nodes, 256 threads. Node MLP + residual, fused
// projection (A/B for next edge pass), zero g_AGG.
// ---------------------------------------------------------------------------
__global__ void __launch_bounds__(256) k_node(
    const float* __restrict__ nw0, const float* __restrict__ nb0,
    const float* __restrict__ nw1, const float* __restrict__ nb1,
    const float* __restrict__ nw2, const float* __restrict__ nb2,
    const float* __restrict__ nwo, const float* __restrict__ nbo,
    const float* __restrict__ ew0, const float* __restrict__ eb0)
{
    __shared__ float sy[2 * 96], sh0[2 * 128], sh1[2 * 64], sh2[2 * 32], sNF[2 * 64];
    const int t = threadIdx.x;
    const int nb2_ = blockIdx.x * 2;

    if (t < 192) {
        int nd = t / 96, c = t % 96;
        sy[t] = (c < 64) ? g_NF[(nb2_ + nd) * 64 + c]
                         : g_AGG[(nb2_ + nd) * 32 + (c - 64)];
    }
    __syncthreads();
    if (t < 64) g_AGG[blockIdx.x * 64 + t] = 0.f;

    const int nd = t >> 7;
    const int o = t & 127;
    // layer 0: 96 -> 128
    {
        float acc = __ldg(nb0 + o);
#pragma unroll 8
        for (int c = 0; c < 96; c++)
            acc = fmaf(sy[nd * 96 + c], __ldg(nw0 + c * 128 + o), acc);
        sh0[nd * 128 + o] = fmaxf(acc, 0.f);
    }
    __syncthreads();
    // layer 1: 128 -> 64
    if (t < 128) {
        const int n1 = t >> 6, o1 = t & 63;
        float acc = __ldg(nb1 + o1);
#pragma unroll 8
        for (int c = 0; c < 128; c++)
            acc = fmaf(sh0[n1 * 128 + c], __ldg(nw1 + c * 64 + o1), acc);
        sh1[n1 * 64 + o1] = fmaxf(acc, 0.f);
    }
    __syncthreads();
    // layer 2: 64 -> 32
    if (t < 64) {
        const int n2 = t >> 5, o2 = t & 31;
        float acc = __ldg(nb2 + o2);
#pragma unroll 8
        for (int c = 0; c < 64; c++)
            acc = fmaf(sh1[n2 * 64 + c], __ldg(nw2 + c * 32 + o2), acc);
        sh2[n2 * 32 + o2] = fmaxf(acc, 0.f);
    }
    __syncthreads();
    // output: 32 -> 64, residual
    if (t < 128) {
        const int n3 = t >> 6, o3 = t & 63;
        float acc = __ldg(nbo + o3);
#pragma unroll 8
        for (int c = 0; c < 32; c++)
            acc = fmaf(sh2[n3 * 32 + c], __ldg(nwo + c * 64 + o3), acc);
        float y = sy[n3 * 96 + o3] + acc;
        g_NF[(nb2_ + n3) * 64 + o3] = y;
        sNF[n3 * 64 + o3] = y;
    }
    __syncthreads();
    // fused projection: A = nf@ew0[0:64], B = nf@ew0[64:128]+eb0
    {
        float a = 0.f, b = 0.f;
#pragma unroll 8
        for (int c = 0; c < 64; c++) {
            float v = sNF[nd * 64 + c];
            a = fmaf(v, __ldg(ew0 + c * 128 + o), a);
            b = fmaf(v, __ldg(ew0 + (64 + c) * 128 + o), b);
        }
        b += __ldg(eb0 + o);
        const int node = nb2_ + nd;
        g_A[node * 128 + o] = a;
        g_B[node * 128 + o] = b;
    }
}

// ---------------------------------------------------------------------------
__global__ void k_read(const float* __restrict__ rw, const float* __restrict__ rb,
                       float* __restrict__ out)
{
    int jn = blockIdx.x * blockDim.x + threadIdx.x;
    if (jn >= NN) return;
    float a0 = rb[0], a1 = rb[1], a2 = rb[2];
#pragma unroll
    for (int c = 0; c < 64; c++) {
        float v = g_NF[jn * FD + c];
        a0 = fmaf(v, rw[c * 3 + 0], a0);
        a1 = fmaf(v, rw[c * 3 + 1], a1);
        a2 = fmaf(v, rw[c * 3 + 2], a2);
    }
    out[jn * 3 + 0] = a0;
    out[jn * 3 + 1] = a1;
    out[jn * 3 + 2] = a2;
}

// ---------------------------------------------------------------------------
extern "C" void kernel_launch(void* const* d_in, const int* in_sizes, int n_in,
                              void* d_out, int out_size)
{
    const float* states = (const float*)d_in[0];
    const float* obj    = (const float*)d_in[1];
    const float* ew0 = (const float*)d_in[2];
    const float* eb0 = (const float*)d_in[3];
    const float* ew1 = (const float*)d_in[4];
    const float* eb1 = (const float*)d_in[5];
    const float* ew2 = (const float*)d_in[6];
    const float* eb2 = (const float*)d_in[7];
    const float* nw0 = (const float*)d_in[8];
    const float* nb0 = (const float*)d_in[9];
    const float* nw1 = (const float*)d_in[10];
    const float* nb1 = (const float*)d_in[11];
    const float* nw2 = (const float*)d_in[12];
    const float* nb2 = (const float*)d_in[13];
    const float* nwo = (const float*)d_in[14];
    const float* nbo = (const float*)d_in[15];
    const float* rw  = (const float*)d_in[16];
    const float* rb  = (const float*)d_in[17];
    float* out = (float*)d_out;

    cudaFuncSetAttribute(k_edge, cudaFuncAttributeMaxDynamicSharedMemorySize,
                         E_SMEMW * (int)sizeof(uint32_t));
    cudaFuncSetAttribute(k_proj, cudaFuncAttributeMaxDynamicSharedMemorySize,
                         PROJ_SMEM * (int)sizeof(float));

    // launch order keeps the 2nd k_edge at index 5 (ncu -s 5 -c 1 capture slot)
    k_init_nf<<<128, 256>>>(states, obj);
    k_init_dist<<<NN, 256>>>(states);
    k_proj<<<64, 256, PROJ_SMEM * (int)sizeof(float)>>>(ew0, eb0);
    for (int it = 0; it < 3; it++) {
        k_edge<<<EGRID, ETHREADS, E_SMEMW * (int)sizeof(uint32_t)>>>(ew0, ew1, eb1, ew2, eb2);
        k_node<<<256, 256>>>(nw0, nb0, nw1, nb1, nw2, nb2, nwo, nbo, ew0, eb0);
    }
    k_read<<<4, 128>>>(rw, rb, out);
}

// round 16
// speedup vs baseline: 1.1296x; 1.1296x over previous
#include <cuda_runtime.h>
#include <cuda_fp16.h>
#include <math.h>
#include <stdint.h>

// ---------------------------------------------------------------------------
// FormationOptimizer: fully-connected GNN, N=512, 3 message-passing rounds.
// Edge layer0 factorized: A[i] + B[j] + dist*wd (fp32). Edge MLP GEMMs on
// tensor cores via mma.sync.m16n8k16 fp16 with ldmatrix fragment loads.
// 1 CTA/SM, 256 threads = 4 independent 2-warp pipelines; W1+W2 in registers;
// H0/H1 double-buffered per pair -> ONE named barrier per item.
// ---------------------------------------------------------------------------

#define NN 512
#define FD 64
#define H0D 128

__device__ float g_NF[NN * FD];
__device__ float g_DIST[NN * NN];
__device__ float g_A[NN * H0D];      // nf @ ew0[0:64]        [node][k]
__device__ float g_B[NN * H0D];      // nf @ ew0[64:128]+eb0  [node][k]
__device__ float g_AGG[NN * 32];

__device__ __forceinline__ uint32_t pack_h2(float lo, float hi) {
    __half2 h = __floats2half2_rn(lo, hi);
    return *(uint32_t*)&h;
}
__device__ __forceinline__ void mma16(float* c, const uint32_t* a, const uint32_t* b) {
    asm volatile(
        "mma.sync.aligned.m16n8k16.row.col.f32.f16.f16.f32 "
        "{%0,%1,%2,%3}, {%4,%5,%6,%7}, {%8,%9}, {%0,%1,%2,%3};"
        : "+f"(c[0]), "+f"(c[1]), "+f"(c[2]), "+f"(c[3])
        : "r"(a[0]), "r"(a[1]), "r"(a[2]), "r"(a[3]), "r"(b[0]), "r"(b[1]));
}
__device__ __forceinline__ void ldsm4(uint32_t* r, uint32_t saddr) {
    asm volatile(
        "ldmatrix.sync.aligned.m8n8.x4.shared.b16 {%0,%1,%2,%3}, [%4];"
        : "=r"(r[0]), "=r"(r[1]), "=r"(r[2]), "=r"(r[3]) : "r"(saddr));
}
__device__ __forceinline__ void pair_bar(int id) {
    asm volatile("bar.sync %0, 64;" :: "r"(id) : "memory");
}

// ---------------------------------------------------------------------------
__global__ void k_init_nf(const float* __restrict__ states,
                          const float* __restrict__ obj) {
    int idx = blockIdx.x * 256 + threadIdx.x;
    int i = idx >> 6, c = idx & 63;
    g_NF[idx] = (c < 6) ? states[i * 6 + c] : obj[c - 6];
}

__global__ void k_init_dist(const float* __restrict__ states) {
    int i = blockIdx.x, t = threadIdx.x;
    float px = states[i * 6 + 0], py = states[i * 6 + 1], pz = states[i * 6 + 2];
    for (int j = t; j < NN; j += blockDim.x) {
        float dx = states[j * 6 + 0] - px;
        float dy = states[j * 6 + 1] - py;
        float dz = states[j * 6 + 2] - pz;
        g_DIST[i * NN + j] = sqrtf(dx * dx + dy * dy + dz * dz);
    }
}

// ---------------------------------------------------------------------------
// k_proj: A/B for iteration 0, zero g_AGG.
// ---------------------------------------------------------------------------
#define PROJ_SMEM (16384 + 512)
__global__ void __launch_bounds__(256) k_proj(const float* __restrict__ ew0,
                                              const float* __restrict__ eb0) {
    extern __shared__ float sm[];
    float* sE = sm;
    float* snf = sm + 16384;
    const int t = threadIdx.x;
    const int nb8 = blockIdx.x * 8;

    for (int q = 0; q < 16; q++)
        *(float4*)(sE + q * 1024 + t * 4) = *(const float4*)(ew0 + q * 1024 + t * 4);
    for (int q = 0; q < 2; q++)
        snf[q * 256 + t] = g_NF[nb8 * 64 + q * 256 + t];
    g_AGG[blockIdx.x * 256 + t] = 0.f;
    __syncthreads();

    const int nd = t >> 5;
    const int k4 = (t & 31) * 4;
    float4 a = make_float4(0.f, 0.f, 0.f, 0.f);
    float4 b = make_float4(0.f, 0.f, 0.f, 0.f);
#pragma unroll 4
    for (int c = 0; c < 64; c++) {
        float v = snf[nd * 64 + c];
        float4 wa = *(const float4*)(sE + c * 128 + k4);
        float4 wb = *(const float4*)(sE + (64 + c) * 128 + k4);
        a.x = fmaf(v, wa.x, a.x); a.y = fmaf(v, wa.y, a.y);
        a.z = fmaf(v, wa.z, a.z); a.w = fmaf(v, wa.w, a.w);
        b.x = fmaf(v, wb.x, b.x); b.y = fmaf(v, wb.y, b.y);
        b.z = fmaf(v, wb.z, b.z); b.w = fmaf(v, wb.w, b.w);
    }
    float4 e = *(const float4*)(eb0 + k4);
    b.x += e.x; b.y += e.y; b.z += e.z; b.w += e.w;
    *(float4*)(g_A + (nb8 + nd) * 128 + k4) = a;
    *(float4*)(g_B + (nb8 + nd) * 128 + k4) = b;
}

// ---------------------------------------------------------------------------
// k_edge: persistent fp16 mma, grid=148 (1 CTA/SM), 256 threads.
// 4 warp-pairs; sub-item = (j, 32-sender tile); H0/H1 double-buffered.
// smem words: W1t[64][68] | W2t[32][36] | 4p x 2buf x H0[32][68]
//             | 4p x 2buf x H1[32][36]
// ---------------------------------------------------------------------------
#define S_W1T 0
#define S_W2T 4352
#define S_H0  5504
#define S_H1  22912
#define E_SMEMW 32128    // words -> 128512 bytes

#define H0BUF (32 * 68)
#define H1BUF (32 * 36)

#define NITEM_S 8192
#define EGRID 148
#define NPAIR 4
#define NPIPE (EGRID * NPAIR)

// H0[e][k] = relu(A[i][k] + B[j][k] + d*wd[k]); warp wp builds rows
// [16*wp, 16*wp+16) of the given 32-edge buffer.
__device__ __forceinline__ void compute_H0(uint32_t* __restrict__ dstbuf,
                                           int s, int wp, int lane,
                                           const float* __restrict__ ew0)
{
    const int j = s >> 4;
    const int eb = (s & 15) * 32 + 16 * wp;
    const float4 wv = __ldg((const float4*)(ew0 + 128 * H0D) + lane);
    float dl = 0.f;
    if (lane < 16) dl = __ldg(g_DIST + j * NN + eb + lane);
    const float4 bv = __ldg((const float4*)(g_B + j * H0D) + lane);
    uint32_t* dst = dstbuf + (16 * wp) * 68 + 2 * lane;
#pragma unroll
    for (int e = 0; e < 16; e++) {
        float d = __shfl_sync(0xffffffffu, dl, e);
        float4 av = __ldg((const float4*)(g_A + (eb + e) * H0D) + lane);
        float h0 = fmaxf(fmaf(d, wv.x, av.x + bv.x), 0.f);
        float h1 = fmaxf(fmaf(d, wv.y, av.y + bv.y), 0.f);
        float h2 = fmaxf(fmaf(d, wv.z, av.z + bv.z), 0.f);
        float h3 = fmaxf(fmaf(d, wv.w, av.w + bv.w), 0.f);
        uint2 u;
        u.x = pack_h2(h0, h1);
        u.y = pack_h2(h2, h3);
        *(uint2*)(dst + e * 68) = u;
    }
}

__global__ void __launch_bounds__(256, 1) k_edge(
    const float* __restrict__ ew0, const float* __restrict__ ew1,
    const float* __restrict__ eb1, const float* __restrict__ ew2,
    const float* __restrict__ eb2)
{
    extern __shared__ uint32_t smw[];
    uint32_t* sW1tw = smw + S_W1T;
    uint32_t* sW2tw = smw + S_W2T;
    const uint32_t sb = (uint32_t)__cvta_generic_to_shared(smw);

    const int t = threadIdx.x;
    const int lane = t & 31;
    const int w = t >> 5;
    const int p  = w >> 1;     // pair 0..3
    const int wp = w & 1;      // warp-in-pair
    const int ar = lane >> 2;
    const int ac = lane & 3;

    uint32_t* sH0p = smw + S_H0 + p * (2 * H0BUF);   // base of buf 0
    uint32_t* sH1p = smw + S_H1 + p * (2 * H1BUF);

    // ---- stage weights (transposed, fp16 pairs) once per CTA ----
    for (int idx = t; idx < 4096; idx += 256) {
        int n = idx >> 6, wk = idx & 63;
        sW1tw[n * 68 + wk] = pack_h2(__ldg(ew1 + (2 * wk) * 64 + n),
                                     __ldg(ew1 + (2 * wk + 1) * 64 + n));
    }
    for (int idx = t; idx < 1024; idx += 256) {
        int m = idx >> 5, wk = idx & 31;
        sW2tw[m * 36 + wk] = pack_h2(__ldg(ew2 + (2 * wk) * 32 + m),
                                     __ldg(ew2 + (2 * wk + 1) * 32 + m));
    }

    // ldmatrix per-lane offsets (word units)
    const int lrowA = ((lane >> 3) & 1) * 8 + (lane & 7);
    const int lcolA = (lane >> 4) * 4;
    const int lrowB = ((lane >> 4) & 1) * 8 + (lane & 7);
    const int lcolB = ((lane >> 3) & 1) * 4;

    // GEMM1: pair tile 32e x 64n; this warp covers n [nw, nw+32)
    const int nw = wp * 32;
    float e1b[4][2];
#pragma unroll
    for (int ni = 0; ni < 4; ni++) {
        e1b[ni][0] = __ldg(eb1 + nw + ni * 8 + 2 * ac);
        e1b[ni][1] = __ldg(eb1 + nw + ni * 8 + 2 * ac + 1);
    }
    // GEMM2: pair tile 32e x 32m; this warp covers m [mb2, mb2+16)
    const int mb2 = wp * 16;
    float e2b[2][2];
#pragma unroll
    for (int ni = 0; ni < 2; ni++) {
        e2b[ni][0] = __ldg(eb2 + mb2 + ni * 8 + 2 * ac);
        e2b[ni][1] = __ldg(eb2 + mb2 + ni * 8 + 2 * ac + 1);
    }

    // ldmatrix base addresses (bytes), buf 0; add buf*BUF*4 dynamically
    const uint32_t aH0_0 = sb + (S_H0 + p * 2 * H0BUF + lrowA * 68 + lcolA) * 4;
    const uint32_t aH0_1 = aH0_0 + 16 * 68 * 4;
    const uint32_t aW1_0 = sb + (S_W1T + (nw + lrowB) * 68 + lcolB) * 4;
    const uint32_t aW1_1 = aW1_0 + 16 * 68 * 4;
    const uint32_t aH1_0 = sb + (S_H1 + p * 2 * H1BUF + lrowA * 36 + lcolA) * 4;
    const uint32_t aH1_1 = aH1_0 + 16 * 36 * 4;
    const uint32_t aW2   = sb + (S_W2T + (mb2 + lrowB) * 36 + lcolB) * 4;

    __syncthreads();   // weights staged (only CTA-wide sync)

    // ---- register-resident fragments: ALL of W1 (64 regs) + W2 (16 regs) ----
    uint32_t w1f[8][8];
#pragma unroll
    for (int ks = 0; ks < 8; ks++) {
        ldsm4(&w1f[ks][0], aW1_0 + ks * 32);
        ldsm4(&w1f[ks][4], aW1_1 + ks * 32);
    }
    uint32_t w2f[4][4];
#pragma unroll
    for (int ks = 0; ks < 4; ks++)
        ldsm4(w2f[ks], aW2 + ks * 32);

    const int bid = p + 1;                 // named barrier id for this pair
    int s = blockIdx.x * NPAIR + p;        // sub-item index for this pipeline
    int buf = 0;
    if (s < NITEM_S)
        compute_H0(sH0p, s, wp, lane, ew0);
    pair_bar(bid);

    while (s < NITEM_S) {
        const int j = s >> 4;
        const int ibase = (s & 15) * 32;
        const uint32_t h0off = (uint32_t)buf * H0BUF * 4;
        const uint32_t h1off = (uint32_t)buf * H1BUF * 4;

        // ================ GEMM1: H1[buf] = relu(H0[buf] @ W1 + b1) ========
        {
            float acc[2][4][4];
#pragma unroll
            for (int mi = 0; mi < 2; mi++)
#pragma unroll
                for (int ni = 0; ni < 4; ni++) {
                    acc[mi][ni][0] = e1b[ni][0];
                    acc[mi][ni][1] = e1b[ni][1];
                    acc[mi][ni][2] = e1b[ni][0];
                    acc[mi][ni][3] = e1b[ni][1];
                }
#pragma unroll
            for (int ks = 0; ks < 8; ks++) {
                const uint32_t koff = h0off + ks * 8 * 4;
                uint32_t a[2][4];
                ldsm4(a[0], aH0_0 + koff);
                ldsm4(a[1], aH0_1 + koff);
#pragma unroll
                for (int mi = 0; mi < 2; mi++)
#pragma unroll
                    for (int ni = 0; ni < 4; ni++)
                        mma16(acc[mi][ni], a[mi],
                              &w1f[ks][(ni >> 1) * 4 + (ni & 1) * 2]);
            }
            // epilogue: relu -> fp16 pairs into H1[buf]
            uint32_t* h1w = sH1p + buf * H1BUF;
#pragma unroll
            for (int mi = 0; mi < 2; mi++) {
                const int r0 = mi * 16 + ar;
#pragma unroll
                for (int ni = 0; ni < 4; ni++) {
                    const int wc = (nw >> 1) + ni * 4 + ac;
                    h1w[r0 * 36 + wc] =
                        pack_h2(fmaxf(acc[mi][ni][0], 0.f), fmaxf(acc[mi][ni][1], 0.f));
                    h1w[(r0 + 8) * 36 + wc] =
                        pack_h2(fmaxf(acc[mi][ni][2], 0.f), fmaxf(acc[mi][ni][3], 0.f));
                }
            }
        }

        // H0 for next sub-item into the other buffer (pre-bar)
        const int nxt = s + NPIPE;
        if (nxt < NITEM_S)
            compute_H0(sH0p + (buf ^ 1) * H0BUF, nxt, wp, lane, ew0);

        pair_bar(bid);   // H1[buf] + H0[buf^1] ready

        // ================ GEMM2 + masked reduction (reads H1[buf]) =========
        {
            float acc[2][2][4];
#pragma unroll
            for (int mi = 0; mi < 2; mi++)
#pragma unroll
                for (int ni = 0; ni < 2; ni++) {
                    acc[mi][ni][0] = e2b[ni][0];
                    acc[mi][ni][1] = e2b[ni][1];
                    acc[mi][ni][2] = e2b[ni][0];
                    acc[mi][ni][3] = e2b[ni][1];
                }
#pragma unroll
            for (int ks = 0; ks < 4; ks++) {
                const uint32_t koff = h1off + ks * 8 * 4;
                uint32_t a[2][4];
                ldsm4(a[0], aH1_0 + koff);
                ldsm4(a[1], aH1_1 + koff);
#pragma unroll
                for (int mi = 0; mi < 2; mi++) {
                    mma16(acc[mi][0], a[mi], &w2f[ks][0]);
                    mma16(acc[mi][1], a[mi], &w2f[ks][2]);
                }
            }
            float sacc[2][2] = {{0.f, 0.f}, {0.f, 0.f}};
#pragma unroll
            for (int mi = 0; mi < 2; mi++) {
                const int i0 = ibase + mi * 16 + ar;
                const bool k0 = (i0 != j);
                const bool k1 = (i0 + 8 != j);
#pragma unroll
                for (int ni = 0; ni < 2; ni++) {
                    if (k0) {
                        sacc[ni][0] += fmaxf(acc[mi][ni][0], 0.f);
                        sacc[ni][1] += fmaxf(acc[mi][ni][1], 0.f);
                    }
                    if (k1) {
                        sacc[ni][0] += fmaxf(acc[mi][ni][2], 0.f);
                        sacc[ni][1] += fmaxf(acc[mi][ni][3], 0.f);
                    }
                }
            }
#pragma unroll
            for (int off = 4; off <= 16; off <<= 1) {
#pragma unroll
                for (int ni = 0; ni < 2; ni++) {
                    sacc[ni][0] += __shfl_xor_sync(0xffffffffu, sacc[ni][0], off);
                    sacc[ni][1] += __shfl_xor_sync(0xffffffffu, sacc[ni][1], off);
                }
            }
            if (lane < 4) {
                float* dst = g_AGG + j * 32 + mb2 + 2 * ac;
                atomicAdd(dst + 0, sacc[0][0]);
                atomicAdd(dst + 1, sacc[0][1]);
                atomicAdd(dst + 8, sacc[1][0]);
                atomicAdd(dst + 9, sacc[1][1]);
            }
        }

        s = nxt;
        buf ^= 1;
    }
}

// ---------------------------------------------------------------------------
// k_node: 256 CTAs x 2 nodes, 256 threads. Node MLP + residual, fused
// projection (A/B for next edge pass), zero g_AGG.
// ---------------------------------------------------------------------------
__global__ void __launch_bounds__(256) k_node(
    const float* __restrict__ nw0, const float* __restrict__ nb0,
    const float* __restrict__ nw1, const float* __restrict__ nb1,
    const float* __restrict__ nw2, const float* __restrict__ nb2,
    const float* __restrict__ nwo, const float* __restrict__ nbo,
    const float* __restrict__ ew0, const float* __restrict__ eb0)
{
    __shared__ float sy[2 * 96], sh0[2 * 128], sh1[2 * 64], sh2[2 * 32], sNF[2 * 64];
    const int t = threadIdx.x;
    const int nb2_ = blockIdx.x * 2;

    if (t < 192) {
        int nd = t / 96, c = t % 96;
        sy[t] = (c < 64) ? g_NF[(nb2_ + nd) * 64 + c]
                         : g_AGG[(nb2_ + nd) * 32 + (c - 64)];
    }
    __syncthreads();
    if (t < 64) g_AGG[blockIdx.x * 64 + t] = 0.f;

    const int nd = t >> 7;
    const int o = t & 127;
    // layer 0: 96 -> 128
    {
        float acc = __ldg(nb0 + o);
#pragma unroll 8
        for (int c = 0; c < 96; c++)
            acc = fmaf(sy[nd * 96 + c], __ldg(nw0 + c * 128 + o), acc);
        sh0[nd * 128 + o] = fmaxf(acc, 0.f);
    }
    __syncthreads();
    // layer 1: 128 -> 64
    if (t < 128) {
        const int n1 = t >> 6, o1 = t & 63;
        float acc = __ldg(nb1 + o1);
#pragma unroll 8
        for (int c = 0; c < 128; c++)
            acc = fmaf(sh0[n1 * 128 + c], __ldg(nw1 + c * 64 + o1), acc);
        sh1[n1 * 64 + o1] = fmaxf(acc, 0.f);
    }
    __syncthreads();
    // layer 2: 64 -> 32
    if (t < 64) {
        const int n2 = t >> 5, o2 = t & 31;
        float acc = __ldg(nb2 + o2);
#pragma unroll 8
        for (int c = 0; c < 64; c++)
            acc = fmaf(sh1[n2 * 64 + c], __ldg(nw2 + c * 32 + o2), acc);
        sh2[n2 * 32 + o2] = fmaxf(acc, 0.f);
    }
    __syncthreads();
    // output: 32 -> 64, residual
    if (t < 128) {
        const int n3 = t >> 6, o3 = t & 63;
        float acc = __ldg(nbo + o3);
#pragma unroll 8
        for (int c = 0; c < 32; c++)
            acc = fmaf(sh2[n3 * 32 + c], __ldg(nwo + c * 64 + o3), acc);
        float y = sy[n3 * 96 + o3] + acc;
        g_NF[(nb2_ + n3) * 64 + o3] = y;
        sNF[n3 * 64 + o3] = y;
    }
    __syncthreads();
    // fused projection: A = nf@ew0[0:64], B = nf@ew0[64:128]+eb0
    {
        float a = 0.f, b = 0.f;
#pragma unroll 8
        for (int c = 0; c < 64; c++) {
            float v = sNF[nd * 64 + c];
            a = fmaf(v, __ldg(ew0 + c * 128 + o), a);
            b = fmaf(v, __ldg(ew0 + (64 + c) * 128 + o), b);
        }
        b += __ldg(eb0 + o);
        const int node = nb2_ + nd;
        g_A[node * 128 + o] = a;
        g_B[node * 128 + o] = b;
    }
}

// ---------------------------------------------------------------------------
__global__ void k_read(const float* __restrict__ rw, const float* __restrict__ rb,
                       float* __restrict__ out)
{
    int jn = blockIdx.x * blockDim.x + threadIdx.x;
    if (jn >= NN) return;
    float a0 = rb[0], a1 = rb[1], a2 = rb[2];
#pragma unroll
    for (int c = 0; c < 64; c++) {
        float v = g_NF[jn * FD + c];
        a0 = fmaf(v, rw[c * 3 + 0], a0);
        a1 = fmaf(v, rw[c * 3 + 1], a1);
        a2 = fmaf(v, rw[c * 3 + 2], a2);
    }
    out[jn * 3 + 0] = a0;
    out[jn * 3 + 1] = a1;
    out[jn * 3 + 2] = a2;
}

// ---------------------------------------------------------------------------
extern "C" void kernel_launch(void* const* d_in, const int* in_sizes, int n_in,
                              void* d_out, int out_size)
{
    const float* states = (const float*)d_in[0];
    const float* obj    = (const float*)d_in[1];
    const float* ew0 = (const float*)d_in[2];
    const float* eb0 = (const float*)d_in[3];
    const float* ew1 = (const float*)d_in[4];
    const float* eb1 = (const float*)d_in[5];
    const float* ew2 = (const float*)d_in[6];
    const float* eb2 = (const float*)d_in[7];
    const float* nw0 = (const float*)d_in[8];
    const float* nb0 = (const float*)d_in[9];
    const float* nw1 = (const float*)d_in[10];
    const float* nb1 = (const float*)d_in[11];
    const float* nw2 = (const float*)d_in[12];
    const float* nb2 = (const float*)d_in[13];
    const float* nwo = (const float*)d_in[14];
    const float* nbo = (const float*)d_in[15];
    const float* rw  = (const float*)d_in[16];
    const float* rb  = (const float*)d_in[17];
    float* out = (float*)d_out;

    cudaFuncSetAttribute(k_edge, cudaFuncAttributeMaxDynamicSharedMemorySize,
                         E_SMEMW * (int)sizeof(uint32_t));
    cudaFuncSetAttribute(k_proj, cudaFuncAttributeMaxDynamicSharedMemorySize,
                         PROJ_SMEM * (int)sizeof(float));

    // launch order keeps the 2nd k_edge at index 5 (ncu -s 5 -c 1 capture slot)
    k_init_nf<<<128, 256>>>(states, obj);
    k_init_dist<<<NN, 256>>>(states);
    k_proj<<<64, 256, PROJ_SMEM * (int)sizeof(float)>>>(ew0, eb0);
    for (int it = 0; it < 3; it++) {
        k_edge<<<EGRID, 256, E_SMEMW * (int)sizeof(uint32_t)>>>(ew0, ew1, eb1, ew2, eb2);
        k_node<<<256, 256>>>(nw0, nb0, nw1, nb1, nw2, nb2, nwo, nbo, ew0, eb0);
    }
    k_read<<<4, 128>>>(rw, rb, out);
}